// round 11
// baseline (speedup 1.0000x reference)
#include <cuda_runtime.h>
#include <cuda_fp16.h>
#include <cstdint>

#define NB 4
#define NC 128
#define NN 8192
#define NKN 16

typedef unsigned long long u64;

// ------------------------- scratch (static device) -------------------------
__device__ __align__(16) float  g_Y[(size_t)NB * NN * 128];   // local half, fp32 [bn][c]
__device__ __align__(16) __half g_E[(size_t)NB * NN * 128];   // edge half, fp16 [bn][c]
__device__ float g_sums[640];   // sumL, sumL2, sumE, sumE2, cross

__device__ __forceinline__ u64 ff2(u64 a, u64 b, u64 c) {
    u64 d;
    asm("fma.rn.f32x2 %0, %1, %2, %3;" : "=l"(d) : "l"(a), "l"(b), "l"(c));
    return d;
}
__device__ __forceinline__ u64 pk2(float x) {
    u64 r;
    asm("mov.b64 %0, {%1, %1};" : "=l"(r) : "f"(x));
    return r;
}
__device__ __forceinline__ float lo32(u64 v) { return __uint_as_float((unsigned)v); }
__device__ __forceinline__ float hi32(u64 v) { return __uint_as_float((unsigned)(v >> 32)); }

// ---------------------------------------------------------------------------
// K1: scalar FFMA2 GEMM (proven R2 kernel, 55.9us). Split epilogue:
// half==0 -> g_Y fp32; half==1 -> g_E fp16.
// ---------------------------------------------------------------------------
__global__ void __launch_bounds__(256) gemm_kernel(
    const float* __restrict__ feat, const float* __restrict__ W1,
    const float* __restrict__ W2)
{
    __shared__ float Wsm[16 * 132];  // [kk][o], padded stride 132
    __shared__ float Fs[16 * 64];    // [kk][n]

    const int tid  = threadIdx.x;
    const int b    = blockIdx.z;
    const int half = blockIdx.y;
    const int n0   = blockIdx.x * 64;

    if (blockIdx.x == 0 && blockIdx.y == 0 && blockIdx.z == 0) {
        for (int i = tid; i < 640; i += 256) g_sums[i] = 0.0f;
    }

    const float* __restrict__ Wg = half ? W2 : W1;

    const int lane = tid & 31;
    const int wrp  = tid >> 5;   // n-group 0..7
    const int r    = tid >> 4;   // Fs row 0..15
    const int cg   = tid & 15;   // Fs col group

    u64 acc2[4][4];
#pragma unroll
    for (int i = 0; i < 4; i++)
#pragma unroll
        for (int j = 0; j < 4; j++) acc2[i][j] = 0ULL;

    for (int k0 = 0; k0 < 128; k0 += 16) {
        float4 fv = *(const float4*)&feat[((size_t)b * NC + k0 + r) * NN + n0 + cg * 4];
        float wv[8];
#pragma unroll
        for (int it = 0; it < 8; it++) {
            int idx = it * 256 + tid;        // 0..2047
            int o = idx >> 4, kk = idx & 15;
            wv[it] = Wg[o * 128 + k0 + kk];
        }
        __syncthreads();
        *(float4*)&Fs[r * 64 + cg * 4] = fv;
#pragma unroll
        for (int it = 0; it < 8; it++) {
            int idx = it * 256 + tid;
            int o = idx >> 4, kk = idx & 15;
            Wsm[kk * 132 + o] = wv[it];
        }
        __syncthreads();

#pragma unroll
        for (int kk = 0; kk < 16; kk++) {
            float4 w4 = *(const float4*)&Wsm[kk * 132 + lane * 4];
            ulonglong2 fa = *(const ulonglong2*)&Fs[kk * 64 + wrp * 8];
            ulonglong2 fb = *(const ulonglong2*)&Fs[kk * 64 + wrp * 8 + 4];
            u64 wp[4] = {pk2(w4.x), pk2(w4.y), pk2(w4.z), pk2(w4.w)};
            u64 f2[4] = {fa.x, fa.y, fb.x, fb.y};
#pragma unroll
            for (int i = 0; i < 4; i++)
#pragma unroll
                for (int j = 0; j < 4; j++)
                    acc2[i][j] = ff2(wp[i], f2[j], acc2[i][j]);
        }
    }

#pragma unroll
    for (int j = 0; j < 4; j++) {
        const int bn = b * NN + n0 + wrp * 8 + 2 * j;
        float4 v0 = make_float4(lo32(acc2[0][j]), lo32(acc2[1][j]),
                                lo32(acc2[2][j]), lo32(acc2[3][j]));
        float4 v1 = make_float4(hi32(acc2[0][j]), hi32(acc2[1][j]),
                                hi32(acc2[2][j]), hi32(acc2[3][j]));
        if (half == 0) {
            *(float4*)&g_Y[(size_t)bn * 128 + lane * 4]       = v0;
            *(float4*)&g_Y[(size_t)(bn + 1) * 128 + lane * 4] = v1;
        } else {
            __half2 p0 = __floats2half2_rn(v0.x, v0.y), p1 = __floats2half2_rn(v0.z, v0.w);
            __half2 q0 = __floats2half2_rn(v1.x, v1.y), q1 = __floats2half2_rn(v1.z, v1.w);
            uint2 u0 = make_uint2(*(uint32_t*)&p0, *(uint32_t*)&p1);
            uint2 u1 = make_uint2(*(uint32_t*)&q0, *(uint32_t*)&q1);
            *(uint2*)&g_E[(size_t)bn * 128 + lane * 4]       = u0;
            *(uint2*)&g_E[(size_t)(bn + 1) * 128 + lane * 4] = u1;
        }
    }
}

// ---------------------------------------------------------------------------
// K2: stats gather. fp16 edge, packed half2 accumulation in the k-loop
// (6 instr/k), folded to fp32 once per bn. Grid-stride, grid 592.
// ---------------------------------------------------------------------------
__global__ void __launch_bounds__(256) stats_kernel(const int* __restrict__ knn)
{
    __shared__ float s[640];
    const int tid = threadIdx.x;
    for (int i = tid; i < 640; i += 256) s[i] = 0.0f;
    __syncthreads();

    const int lane = tid & 31, wrp = tid >> 5;
    const int c4 = lane * 4;
    const int stride = gridDim.x * 8;
    const __half2 hz = __float2half2_rn(0.0f);

    float4 aL = {0,0,0,0}, aL2 = {0,0,0,0}, aE = {0,0,0,0};
    float4 aE2 = {0,0,0,0}, aX = {0,0,0,0};

    for (int bn = blockIdx.x * 8 + wrp; bn < NB * NN; bn += stride) {
        int my_idx = 0;
        if (lane < 16) my_idx = knn[bn * NKN + lane];
        const float4 l = *(const float4*)&g_Y[(size_t)bn * 128 + c4];
        const int boff = bn & ~(NN - 1);
        __half2 Sh0 = hz, Sh1 = hz, Qh0 = hz, Qh1 = hz;
#pragma unroll
        for (int k = 0; k < 16; k++) {
            const int m = __shfl_sync(0xffffffffu, my_idx, k);
            const uint2 ev = *(const uint2*)&g_E[((size_t)(boff + m)) * 128 + c4];
            const __half2 e0 = *(const __half2*)&ev.x;
            const __half2 e1 = *(const __half2*)&ev.y;
            Sh0 = __hadd2(Sh0, e0);
            Sh1 = __hadd2(Sh1, e1);
            Qh0 = __hfma2(e0, e0, Qh0);
            Qh1 = __hfma2(e1, e1, Qh1);
        }
        const float2 s01 = __half22float2(Sh0), s23 = __half22float2(Sh1);
        const float2 q01 = __half22float2(Qh0), q23 = __half22float2(Qh1);
        aE.x += s01.x; aE.y += s01.y; aE.z += s23.x; aE.w += s23.y;
        aE2.x += q01.x; aE2.y += q01.y; aE2.z += q23.x; aE2.w += q23.y;
        aX.x = fmaf(s01.x, l.x, aX.x); aX.y = fmaf(s01.y, l.y, aX.y);
        aX.z = fmaf(s23.x, l.z, aX.z); aX.w = fmaf(s23.y, l.w, aX.w);
        aL.x += l.x; aL.y += l.y; aL.z += l.z; aL.w += l.w;
        aL2.x = fmaf(l.x, l.x, aL2.x); aL2.y = fmaf(l.y, l.y, aL2.y);
        aL2.z = fmaf(l.z, l.z, aL2.z); aL2.w = fmaf(l.w, l.w, aL2.w);
    }

    atomicAdd(&s[c4 + 0], aL.x);  atomicAdd(&s[c4 + 1], aL.y);
    atomicAdd(&s[c4 + 2], aL.z);  atomicAdd(&s[c4 + 3], aL.w);
    atomicAdd(&s[128 + c4 + 0], aL2.x); atomicAdd(&s[128 + c4 + 1], aL2.y);
    atomicAdd(&s[128 + c4 + 2], aL2.z); atomicAdd(&s[128 + c4 + 3], aL2.w);
    atomicAdd(&s[256 + c4 + 0], aE.x);  atomicAdd(&s[256 + c4 + 1], aE.y);
    atomicAdd(&s[256 + c4 + 2], aE.z);  atomicAdd(&s[256 + c4 + 3], aE.w);
    atomicAdd(&s[384 + c4 + 0], aE2.x); atomicAdd(&s[384 + c4 + 1], aE2.y);
    atomicAdd(&s[384 + c4 + 2], aE2.z); atomicAdd(&s[384 + c4 + 3], aE2.w);
    atomicAdd(&s[512 + c4 + 0], aX.x);  atomicAdd(&s[512 + c4 + 1], aX.y);
    atomicAdd(&s[512 + c4 + 2], aX.z);  atomicAdd(&s[512 + c4 + 3], aX.w);
    __syncthreads();
    for (int i = tid; i < 640; i += 256) atomicAdd(&g_sums[i], s[i]);
}

// ---------------------------------------------------------------------------
// K3: output gather. Edge channels in packed half2 (sub/fma/max/add = 8 ops/k),
// folded to fp32 every 8 k's. Local channels exact fp32.
// ---------------------------------------------------------------------------
__global__ void __launch_bounds__(256) output_kernel(const int* __restrict__ knn,
                                                     const float* __restrict__ gamma,
                                                     const float* __restrict__ beta,
                                                     float* __restrict__ out)
{
    __shared__ float tile[32 * 257];
    __shared__ float sa[256], sb[256];
    const int tid = threadIdx.x, lane = tid & 31, wrp = tid >> 5;
    const int c4 = lane * 4;
    const int bn0 = blockIdx.x * 32;
    const __half2 hz = __float2half2_rn(0.0f);

    {   // replicated finalize
        const int c = tid;
        const float invBN  = 1.0f / (float)(NB * NN);
        const float invBNK = 1.0f / (float)((size_t)NB * NN * NKN);
        float mean, var;
        if (c < 128) {
            float sL = g_sums[c], sL2 = g_sums[128 + c];
            mean = sL * invBN;
            var  = sL2 * invBN - mean * mean;
        } else {
            int cc = c - 128;
            float sL  = g_sums[cc],       sL2 = g_sums[128 + cc];
            float sE  = g_sums[256 + cc], sE2 = g_sums[384 + cc];
            float sX  = g_sums[512 + cc];
            float sD  = sE - (float)NKN * sL;
            float sD2 = sE2 - 2.0f * sX + (float)NKN * sL2;
            mean = sD * invBNK;
            var  = sD2 * invBNK - mean * mean;
        }
        float a = gamma[c] * rsqrtf(var + 1e-5f);
        sa[c] = a;
        sb[c] = beta[c] - mean * a;
    }
    __syncthreads();

    const float4 a1 = *(const float4*)&sa[c4];
    const float4 b1 = *(const float4*)&sb[c4];
    const __half2 a2h0 = __floats2half2_rn(sa[128 + c4 + 0], sa[128 + c4 + 1]);
    const __half2 a2h1 = __floats2half2_rn(sa[128 + c4 + 2], sa[128 + c4 + 3]);
    const __half2 b2h0 = __floats2half2_rn(sb[128 + c4 + 0], sb[128 + c4 + 1]);
    const __half2 b2h1 = __floats2half2_rn(sb[128 + c4 + 2], sb[128 + c4 + 3]);

    for (int t = 0; t < 4; t++) {
        const int col = wrp * 4 + t;
        const int bn = bn0 + col;
        int my_idx = 0;
        if (lane < 16) my_idx = knn[bn * NKN + lane];
        const float4 l = *(const float4*)&g_Y[(size_t)bn * 128 + c4];
        const __half2 lh0 = __floats2half2_rn(l.x, l.y);
        const __half2 lh1 = __floats2half2_rn(l.z, l.w);
        const int boff = bn & ~(NN - 1);

        float2 F0 = {0.0f, 0.0f}, F1 = {0.0f, 0.0f};
        __half2 Sh0 = hz, Sh1 = hz;
#pragma unroll
        for (int k = 0; k < 16; k++) {
            const int m = __shfl_sync(0xffffffffu, my_idx, k);
            const uint2 ev = *(const uint2*)&g_E[((size_t)(boff + m)) * 128 + c4];
            const __half2 e0 = *(const __half2*)&ev.x;
            const __half2 e1 = *(const __half2*)&ev.y;
            Sh0 = __hadd2(Sh0, __hmax2(__hfma2(a2h0, __hsub2(e0, lh0), b2h0), hz));
            Sh1 = __hadd2(Sh1, __hmax2(__hfma2(a2h1, __hsub2(e1, lh1), b2h1), hz));
            if (k == 7) {
                const float2 f0 = __half22float2(Sh0), f1 = __half22float2(Sh1);
                F0.x += f0.x; F0.y += f0.y; F1.x += f1.x; F1.y += f1.y;
                Sh0 = hz; Sh1 = hz;
            }
        }
        {
            const float2 f0 = __half22float2(Sh0), f1 = __half22float2(Sh1);
            F0.x += f0.x; F0.y += f0.y; F1.x += f1.x; F1.y += f1.y;
        }

        tile[col * 257 + c4 + 0] = fmaxf(fmaf(a1.x, l.x, b1.x), 0.0f);
        tile[col * 257 + c4 + 1] = fmaxf(fmaf(a1.y, l.y, b1.y), 0.0f);
        tile[col * 257 + c4 + 2] = fmaxf(fmaf(a1.z, l.z, b1.z), 0.0f);
        tile[col * 257 + c4 + 3] = fmaxf(fmaf(a1.w, l.w, b1.w), 0.0f);
        const float inv = 1.0f / 16.0f;
        tile[col * 257 + 128 + c4 + 0] = F0.x * inv;
        tile[col * 257 + 128 + c4 + 1] = F0.y * inv;
        tile[col * 257 + 128 + c4 + 2] = F1.x * inv;
        tile[col * 257 + 128 + c4 + 3] = F1.y * inv;
    }
    __syncthreads();

    const int b = bn0 >> 13;          // NN = 8192
    const int n0 = bn0 & (NN - 1);
#pragma unroll 4
    for (int i = 0; i < 32; i++) {
        int j = i * 256 + tid;
        int row = j >> 5, col = j & 31;
        out[((size_t)(b * 256 + row)) * NN + n0 + col] = tile[col * 257 + row];
    }
}

extern "C" void kernel_launch(void* const* d_in, const int* in_sizes, int n_in,
                              void* d_out, int out_size)
{
    const float* feat  = (const float*)d_in[0];
    const int*   knn   = (const int*)d_in[1];
    const float* W1    = (const float*)d_in[2];
    const float* W2    = (const float*)d_in[3];
    const float* gamma = (const float*)d_in[4];
    const float* beta  = (const float*)d_in[5];
    float* out = (float*)d_out;

    gemm_kernel<<<dim3(NN / 64, 2, NB), 256>>>(feat, W1, W2);
    stats_kernel<<<592, 256>>>(knn);
    output_kernel<<<1024, 256>>>(knn, gamma, beta, out);
}

// round 12
// speedup vs baseline: 1.3575x; 1.3575x over previous
#include <cuda_runtime.h>
#include <cstdint>

#define NB 4
#define NC 128
#define NN 8192
#define NKN 16

typedef unsigned long long u64;

// ------------------------- scratch (static device) -------------------------
__device__ __align__(16) float g_Y[(size_t)NB * NN * 256];  // [bn][c] c<128 local, c>=128 edge
__device__ float g_sums[640];   // sumL, sumL2, sumE, sumE2, cross

__device__ __forceinline__ u64 ff2(u64 a, u64 b, u64 c) {
    u64 d;
    asm("fma.rn.f32x2 %0, %1, %2, %3;" : "=l"(d) : "l"(a), "l"(b), "l"(c));
    return d;
}
__device__ __forceinline__ u64 pk2(float x) {
    u64 r;
    asm("mov.b64 %0, {%1, %1};" : "=l"(r) : "f"(x));
    return r;
}
__device__ __forceinline__ float lo32(u64 v) { return __uint_as_float((unsigned)v); }
__device__ __forceinline__ float hi32(u64 v) { return __uint_as_float((unsigned)(v >> 32)); }

// ---------------------------------------------------------------------------
// K1: FFMA2 GEMM, 8x8 thread tile (2B smem per FFMA2 -> crossbar no longer
// binding). Single smem buffer, register prefetch of next K-chunk during
// compute. Block tile: O=128 (one half) x N=128. Grid (64, 2, 4) = 512.
// ---------------------------------------------------------------------------
__global__ void __launch_bounds__(256, 2) gemm_kernel(
    const float* __restrict__ feat, const float* __restrict__ W1,
    const float* __restrict__ W2)
{
    __shared__ float Wsm[16 * 132];  // [kk][o], padded stride 132 (8448 B)
    __shared__ float Fs[16 * 128];   // [kk][n]                    (8192 B)

    const int tid  = threadIdx.x;
    const int b    = blockIdx.z;
    const int half = blockIdx.y;
    const int n0   = blockIdx.x * 128;

    if (blockIdx.x == 0 && blockIdx.y == 0 && blockIdx.z == 0) {
        for (int i = tid; i < 640; i += 256) g_sums[i] = 0.0f;
    }

    const float* __restrict__ Wg = half ? W2 : W1;

    const int o0 = (tid & 15) * 8;   // 8 consecutive o per thread
    const int nb = (tid >> 4) * 8;   // 8 consecutive n per thread
    const int r  = tid >> 4;         // staging row 0..15
    const int cg = tid & 15;         // staging col group (8 floats)

    u64 acc2[8][4];
#pragma unroll
    for (int i = 0; i < 8; i++)
#pragma unroll
        for (int j = 0; j < 4; j++) acc2[i][j] = 0ULL;

    const float* fbase = &feat[(size_t)b * NC * NN + n0];

    // prologue: load chunk 0 into registers
    float4 pfa = *(const float4*)&fbase[(size_t)r * NN + cg * 8];
    float4 pfb = *(const float4*)&fbase[(size_t)r * NN + cg * 8 + 4];
    float pw[8];
#pragma unroll
    for (int it = 0; it < 8; it++) {
        int idx = it * 256 + tid;
        int o = idx >> 4, kk = idx & 15;
        pw[it] = Wg[o * 128 + kk];
    }

    for (int kc = 0; kc < 8; kc++) {
        __syncthreads();             // previous compute done; safe to overwrite
        *(float4*)&Fs[r * 128 + cg * 8]     = pfa;
        *(float4*)&Fs[r * 128 + cg * 8 + 4] = pfb;
#pragma unroll
        for (int it = 0; it < 8; it++) {
            int idx = it * 256 + tid;
            int o = idx >> 4, kk = idx & 15;
            Wsm[kk * 132 + o] = pw[it];
        }
        __syncthreads();

        // prefetch next chunk (LDG latency hidden under compute)
        if (kc < 7) {
            const int k0 = (kc + 1) * 16;
            pfa = *(const float4*)&fbase[(size_t)(k0 + r) * NN + cg * 8];
            pfb = *(const float4*)&fbase[(size_t)(k0 + r) * NN + cg * 8 + 4];
#pragma unroll
            for (int it = 0; it < 8; it++) {
                int idx = it * 256 + tid;
                int o = idx >> 4, kk = idx & 15;
                pw[it] = Wg[o * 128 + k0 + kk];
            }
        }

#pragma unroll
        for (int kk = 0; kk < 16; kk++) {
            float4 wa = *(const float4*)&Wsm[kk * 132 + o0];
            float4 wb = *(const float4*)&Wsm[kk * 132 + o0 + 4];
            ulonglong2 f01 = *(const ulonglong2*)&Fs[kk * 128 + nb];
            ulonglong2 f23 = *(const ulonglong2*)&Fs[kk * 128 + nb + 4];
            u64 wp[8] = {pk2(wa.x), pk2(wa.y), pk2(wa.z), pk2(wa.w),
                         pk2(wb.x), pk2(wb.y), pk2(wb.z), pk2(wb.w)};
            u64 f2[4] = {f01.x, f01.y, f23.x, f23.y};
#pragma unroll
            for (int i = 0; i < 8; i++)
#pragma unroll
                for (int j = 0; j < 4; j++)
                    acc2[i][j] = ff2(wp[i], f2[j], acc2[i][j]);
        }
    }

    // epilogue: Y[bn][half*128 + o0..o0+7], fp32 interleaved (proven layout)
#pragma unroll
    for (int j = 0; j < 4; j++) {
        size_t row = ((size_t)(b * NN + n0 + nb + 2 * j)) * 256 + half * 128 + o0;
        float4 v0a = make_float4(lo32(acc2[0][j]), lo32(acc2[1][j]),
                                 lo32(acc2[2][j]), lo32(acc2[3][j]));
        float4 v0b = make_float4(lo32(acc2[4][j]), lo32(acc2[5][j]),
                                 lo32(acc2[6][j]), lo32(acc2[7][j]));
        float4 v1a = make_float4(hi32(acc2[0][j]), hi32(acc2[1][j]),
                                 hi32(acc2[2][j]), hi32(acc2[3][j]));
        float4 v1b = make_float4(hi32(acc2[4][j]), hi32(acc2[5][j]),
                                 hi32(acc2[6][j]), hi32(acc2[7][j]));
        *(float4*)&g_Y[row]           = v0a;
        *(float4*)&g_Y[row + 4]       = v0b;
        *(float4*)&g_Y[row + 256]     = v1a;
        *(float4*)&g_Y[row + 256 + 4] = v1b;
    }
}

// ---------------------------------------------------------------------------
// K2: stats gather (exact copy of the 100.2us-config kernel; fp32)
// ---------------------------------------------------------------------------
__global__ void __launch_bounds__(256) stats_kernel(const int* __restrict__ knn)
{
    __shared__ float s[640];
    const int tid = threadIdx.x;
    for (int i = tid; i < 640; i += 256) s[i] = 0.0f;
    __syncthreads();

    const int lane = tid & 31, wrp = tid >> 5;
    const int c4 = lane * 4;
    const int stride = gridDim.x * 8;

    float4 aL = {0,0,0,0}, aL2 = {0,0,0,0}, aE = {0,0,0,0};
    float4 aE2 = {0,0,0,0}, aX = {0,0,0,0};

    for (int bn = blockIdx.x * 8 + wrp; bn < NB * NN; bn += stride) {
        int my_idx = 0;
        if (lane < 16) my_idx = knn[bn * NKN + lane];
        const float4 l = *(const float4*)&g_Y[(size_t)bn * 256 + c4];
        const int boff = bn & ~(NN - 1);
        float4 S = {0,0,0,0}, Q = {0,0,0,0};
#pragma unroll
        for (int k = 0; k < 16; k++) {
            const int m = __shfl_sync(0xffffffffu, my_idx, k);
            const float4 e = *(const float4*)&g_Y[((size_t)(boff + m)) * 256 + 128 + c4];
            S.x += e.x; S.y += e.y; S.z += e.z; S.w += e.w;
            Q.x = fmaf(e.x, e.x, Q.x); Q.y = fmaf(e.y, e.y, Q.y);
            Q.z = fmaf(e.z, e.z, Q.z); Q.w = fmaf(e.w, e.w, Q.w);
        }
        aE.x += S.x; aE.y += S.y; aE.z += S.z; aE.w += S.w;
        aE2.x += Q.x; aE2.y += Q.y; aE2.z += Q.z; aE2.w += Q.w;
        aX.x = fmaf(S.x, l.x, aX.x); aX.y = fmaf(S.y, l.y, aX.y);
        aX.z = fmaf(S.z, l.z, aX.z); aX.w = fmaf(S.w, l.w, aX.w);
        aL.x += l.x; aL.y += l.y; aL.z += l.z; aL.w += l.w;
        aL2.x = fmaf(l.x, l.x, aL2.x); aL2.y = fmaf(l.y, l.y, aL2.y);
        aL2.z = fmaf(l.z, l.z, aL2.z); aL2.w = fmaf(l.w, l.w, aL2.w);
    }

    atomicAdd(&s[c4 + 0], aL.x);  atomicAdd(&s[c4 + 1], aL.y);
    atomicAdd(&s[c4 + 2], aL.z);  atomicAdd(&s[c4 + 3], aL.w);
    atomicAdd(&s[128 + c4 + 0], aL2.x); atomicAdd(&s[128 + c4 + 1], aL2.y);
    atomicAdd(&s[128 + c4 + 2], aL2.z); atomicAdd(&s[128 + c4 + 3], aL2.w);
    atomicAdd(&s[256 + c4 + 0], aE.x);  atomicAdd(&s[256 + c4 + 1], aE.y);
    atomicAdd(&s[256 + c4 + 2], aE.z);  atomicAdd(&s[256 + c4 + 3], aE.w);
    atomicAdd(&s[384 + c4 + 0], aE2.x); atomicAdd(&s[384 + c4 + 1], aE2.y);
    atomicAdd(&s[384 + c4 + 2], aE2.z); atomicAdd(&s[384 + c4 + 3], aE2.w);
    atomicAdd(&s[512 + c4 + 0], aX.x);  atomicAdd(&s[512 + c4 + 1], aX.y);
    atomicAdd(&s[512 + c4 + 2], aX.z);  atomicAdd(&s[512 + c4 + 3], aX.w);
    __syncthreads();
    for (int i = tid; i < 640; i += 256) atomicAdd(&g_sums[i], s[i]);
}

// ---------------------------------------------------------------------------
// K3: output gather (exact copy of the 100.2us-config kernel; fp32)
// ---------------------------------------------------------------------------
__global__ void __launch_bounds__(256) output_kernel(const int* __restrict__ knn,
                                                     const float* __restrict__ gamma,
                                                     const float* __restrict__ beta,
                                                     float* __restrict__ out)
{
    __shared__ float tile[32 * 257];
    __shared__ float sa[256], sb[256];
    const int tid = threadIdx.x, lane = tid & 31, wrp = tid >> 5;
    const int c4 = lane * 4;
    const int bn0 = blockIdx.x * 32;

    {   // replicated finalize
        const int c = tid;
        const float invBN  = 1.0f / (float)(NB * NN);
        const float invBNK = 1.0f / (float)((size_t)NB * NN * NKN);
        float mean, var;
        if (c < 128) {
            float sL = g_sums[c], sL2 = g_sums[128 + c];
            mean = sL * invBN;
            var  = sL2 * invBN - mean * mean;
        } else {
            int cc = c - 128;
            float sL  = g_sums[cc],       sL2 = g_sums[128 + cc];
            float sE  = g_sums[256 + cc], sE2 = g_sums[384 + cc];
            float sX  = g_sums[512 + cc];
            float sD  = sE - (float)NKN * sL;
            float sD2 = sE2 - 2.0f * sX + (float)NKN * sL2;
            mean = sD * invBNK;
            var  = sD2 * invBNK - mean * mean;
        }
        float a = gamma[c] * rsqrtf(var + 1e-5f);
        sa[c] = a;
        sb[c] = beta[c] - mean * a;
    }
    __syncthreads();

    const float4 a1 = *(const float4*)&sa[c4];
    const float4 b1 = *(const float4*)&sb[c4];
    const float4 a2 = *(const float4*)&sa[128 + c4];
    const float4 b2 = *(const float4*)&sb[128 + c4];

    for (int t = 0; t < 4; t++) {
        const int col = wrp * 4 + t;
        const int bn = bn0 + col;
        int my_idx = 0;
        if (lane < 16) my_idx = knn[bn * NKN + lane];
        const float4 l = *(const float4*)&g_Y[(size_t)bn * 256 + c4];
        const int boff = bn & ~(NN - 1);
        float4 S = {0,0,0,0};
#pragma unroll
        for (int k = 0; k < 16; k++) {
            const int m = __shfl_sync(0xffffffffu, my_idx, k);
            const float4 e = *(const float4*)&g_Y[((size_t)(boff + m)) * 256 + 128 + c4];
            S.x += fmaxf(fmaf(a2.x, e.x - l.x, b2.x), 0.0f);
            S.y += fmaxf(fmaf(a2.y, e.y - l.y, b2.y), 0.0f);
            S.z += fmaxf(fmaf(a2.z, e.z - l.z, b2.z), 0.0f);
            S.w += fmaxf(fmaf(a2.w, e.w - l.w, b2.w), 0.0f);
        }
        tile[col * 257 + c4 + 0] = fmaxf(fmaf(a1.x, l.x, b1.x), 0.0f);
        tile[col * 257 + c4 + 1] = fmaxf(fmaf(a1.y, l.y, b1.y), 0.0f);
        tile[col * 257 + c4 + 2] = fmaxf(fmaf(a1.z, l.z, b1.z), 0.0f);
        tile[col * 257 + c4 + 3] = fmaxf(fmaf(a1.w, l.w, b1.w), 0.0f);
        const float inv = 1.0f / 16.0f;
        tile[col * 257 + 128 + c4 + 0] = S.x * inv;
        tile[col * 257 + 128 + c4 + 1] = S.y * inv;
        tile[col * 257 + 128 + c4 + 2] = S.z * inv;
        tile[col * 257 + 128 + c4 + 3] = S.w * inv;
    }
    __syncthreads();

    const int b = bn0 >> 13;          // NN = 8192
    const int n0 = bn0 & (NN - 1);
#pragma unroll 4
    for (int i = 0; i < 32; i++) {
        int j = i * 256 + tid;
        int row = j >> 5, col = j & 31;
        out[((size_t)(b * 256 + row)) * NN + n0 + col] = tile[col * 257 + row];
    }
}

extern "C" void kernel_launch(void* const* d_in, const int* in_sizes, int n_in,
                              void* d_out, int out_size)
{
    const float* feat  = (const float*)d_in[0];
    const int*   knn   = (const int*)d_in[1];
    const float* W1    = (const float*)d_in[2];
    const float* W2    = (const float*)d_in[3];
    const float* gamma = (const float*)d_in[4];
    const float* beta  = (const float*)d_in[5];
    float* out = (float*)d_out;

    gemm_kernel<<<dim3(NN / 128, 2, NB), 256>>>(feat, W1, W2);
    stats_kernel<<<592, 256>>>(knn);
    output_kernel<<<1024, 256>>>(knn, gamma, beta, out);
}